// round 16
// baseline (speedup 1.0000x reference)
#include <cuda_runtime.h>
#include <cuda_fp16.h>
#include <cstdint>

#define NB 16
#define CC 512
#define CPD 64
#define NN 4096

// scratch (static __device__ — no allocation)
__device__ __half g_V[(size_t)NB * CPD * NN];
__device__ float  g_P[(size_t)NB * 64 * CPD * CPD]; // energy partials (64 n-slices)
__device__ float  g_E[NB * CPD * CPD];              // softmaxed attention A
__device__ __half g_M[NB * CC * CPD];               // M = Wo @ A (fp16)
__device__ __half g_W[192 * 512];                   // fp16 Wqkv

__device__ __forceinline__ void cp_async16(void* smem, const void* gmem) {
    uint32_t s = (uint32_t)__cvta_generic_to_shared(smem);
    asm volatile("cp.async.cg.shared.global [%0], [%1], 16;\n" :: "r"(s), "l"(gmem));
}
#define CP_COMMIT() asm volatile("cp.async.commit_group;\n" ::: "memory")
#define CP_WAIT(n)  asm volatile("cp.async.wait_group %0;\n" :: "n"(n) : "memory")

__device__ __forceinline__ void mma16(float c[4], const uint32_t a[4], const uint32_t b[2]) {
    asm volatile(
        "mma.sync.aligned.m16n8k16.row.col.f32.f16.f16.f32 "
        "{%0,%1,%2,%3},{%4,%5,%6,%7},{%8,%9},{%0,%1,%2,%3};"
        : "+f"(c[0]), "+f"(c[1]), "+f"(c[2]), "+f"(c[3])
        : "r"(a[0]), "r"(a[1]), "r"(a[2]), "r"(a[3]), "r"(b[0]), "r"(b[1]));
}

__device__ __forceinline__ void ldsm_x4(uint32_t r[4], uint32_t smaddr) {
    asm volatile("ldmatrix.sync.aligned.m8n8.x4.shared.b16 {%0,%1,%2,%3}, [%4];"
        : "=r"(r[0]), "=r"(r[1]), "=r"(r[2]), "=r"(r[3]) : "r"(smaddr));
}

__device__ __forceinline__ void sth2(__half* p, float a, float b) {
    *reinterpret_cast<__half2*>(p) = __floats2half2_rn(a, b);
}

// ============================================================================
// K0: convert Wqkv -> fp16 g_W. grid 96, 256 threads
// ============================================================================
__global__ __launch_bounds__(256) void wconv_kernel(
    const float* __restrict__ wq, const float* __restrict__ wk, const float* __restrict__ wv)
{
    int f = (blockIdx.x * 256 + threadIdx.x) * 4;
    int r = f >> 9, c = f & 511;
    const float* w = r < 64 ? wq + (size_t)r * 512
                   : r < 128 ? wk + (size_t)(r - 64) * 512
                             : wv + (size_t)(r - 128) * 512;
    float4 t = *reinterpret_cast<const float4*>(w + c);
    __half2 h0 = __floats2half2_rn(t.x, t.y);
    __half2 h1 = __floats2half2_rn(t.z, t.w);
    uint2 u;
    u.x = *reinterpret_cast<uint32_t*>(&h0);
    u.y = *reinterpret_cast<uint32_t*>(&h1);
    *reinterpret_cast<uint2*>(g_W + (size_t)r * 512 + c) = u;
}

// ============================================================================
// K1: fused QKV + energy. 256 threads (8 warps: 4m x 2n), tile 192x64, BK=32,
// 16 iters, triple-buffered A/S, double-buffered B. 2 CTAs/SM. (AT MAC FLOOR)
// ============================================================================
#define K1_AS(i) ((i) * 15360)
#define K1_SS(i) (46080 + (i) * 8704)
#define K1_BS(i) (72192 + (i) * 5120)
#define K1_SMEMB 82432

__device__ __forceinline__ void k1_transpose(char* smc, int s_slot, int b_buf, int tid) {
    const float* S = reinterpret_cast<const float*>(smc + K1_SS(s_slot));
    __half* Bd = reinterpret_cast<__half*>(smc + K1_BS(b_buf));
    const int n = tid & 63, kb = (tid >> 6) * 8;
    const float* col = S + n;
    float v0 = col[(kb + 0) * 68], v1 = col[(kb + 1) * 68];
    float v2 = col[(kb + 2) * 68], v3 = col[(kb + 3) * 68];
    float v4 = col[(kb + 4) * 68], v5 = col[(kb + 5) * 68];
    float v6 = col[(kb + 6) * 68], v7 = col[(kb + 7) * 68];
    __half2 h0 = __floats2half2_rn(v0, v1), h1 = __floats2half2_rn(v2, v3);
    __half2 h2 = __floats2half2_rn(v4, v5), h3 = __floats2half2_rn(v6, v7);
    uint4 u;
    u.x = *reinterpret_cast<uint32_t*>(&h0);
    u.y = *reinterpret_cast<uint32_t*>(&h1);
    u.z = *reinterpret_cast<uint32_t*>(&h2);
    u.w = *reinterpret_cast<uint32_t*>(&h3);
    *reinterpret_cast<uint4*>(Bd + n * 40 + kb) = u;
}

__device__ __forceinline__ void k1_issue_stage(char* smc, int slot, int k0,
                                               const float* Xb, int n0, int tid) {
    char* Ad = smc + K1_AS(slot);
    char* Sd = smc + K1_SS(slot);
#pragma unroll
    for (int i = 0; i < 3; i++) {
        int v = tid + i * 256, r = v >> 2, kv = v & 3;
        cp_async16(Ad + r * 80 + kv * 16, g_W + (size_t)r * 512 + k0 + kv * 8);
    }
#pragma unroll
    for (int i = 0; i < 2; i++) {
        int v = tid + i * 256, k = v >> 4, nv = v & 15;
        cp_async16(Sd + k * 272 + nv * 16, Xb + (size_t)(k0 + k) * NN + n0 + nv * 4);
    }
    CP_COMMIT();
}

__global__ __launch_bounds__(256, 2) void qkv_energy_kernel(
    const float* __restrict__ x,
    const float* __restrict__ bq, const float* __restrict__ bk, const float* __restrict__ bv)
{
    extern __shared__ char smc[];
    const int b = blockIdx.y;
    const int n0 = blockIdx.x * 64;
    const float* Xb = x + (size_t)b * CC * NN;

    const int tid = threadIdx.x;
    const int lane = tid & 31, warp = tid >> 5;
    const int wm = (warp & 3) * 48;
    const int wn = (warp >> 2) * 32;
    const int gid = lane >> 2, tig = lane & 3;
    const int lrow = lane & 15, lkb = (lane >> 4) * 16;

    float acc[3][4][4];
#pragma unroll
    for (int i = 0; i < 3; i++)
#pragma unroll
        for (int j = 0; j < 4; j++)
#pragma unroll
            for (int q = 0; q < 4; q++) acc[i][j][q] = 0.f;

    k1_issue_stage(smc, 0, 0, Xb, n0, tid);
    k1_issue_stage(smc, 1, 32, Xb, n0, tid);
    k1_issue_stage(smc, 2, 64, Xb, n0, tid);
    CP_WAIT(2);
    __syncthreads();
    k1_transpose(smc, 0, 0, tid);
    __syncthreads();

    const uint32_t smcBase = (uint32_t)__cvta_generic_to_shared(smc);

    for (int kt = 0; kt < 16; kt++) {
        const int a_slot = kt % 3;
        const int bbuf = kt & 1;

        if (kt <= 13) { CP_WAIT(1); }
        else if (kt == 14) { CP_WAIT(0); }
        __syncthreads();

        if (kt < 15) k1_transpose(smc, (kt + 1) % 3, (kt + 1) & 1, tid);

        const uint32_t aBase = smcBase + K1_AS(a_slot);
        const uint32_t bBase = smcBase + K1_BS(bbuf);
#pragma unroll
        for (int kk = 0; kk < 2; kk++) {
            uint32_t af[3][4], bt[2][4];
#pragma unroll
            for (int mi = 0; mi < 3; mi++)
                ldsm_x4(af[mi], aBase + (wm + mi * 16 + lrow) * 80 + kk * 32 + lkb);
#pragma unroll
            for (int t = 0; t < 2; t++)
                ldsm_x4(bt[t], bBase + (wn + t * 16 + lrow) * 80 + kk * 32 + lkb);
#pragma unroll
            for (int mi = 0; mi < 3; mi++)
#pragma unroll
                for (int ni = 0; ni < 4; ni++) {
                    uint32_t bb[2] = { bt[ni >> 1][ni & 1], bt[ni >> 1][(ni & 1) + 2] };
                    mma16(acc[mi][ni], af[mi], bb);
                }
        }
        __syncthreads();

        if (kt <= 12)
            k1_issue_stage(smc, a_slot, (kt + 3) * 32, Xb, n0, tid);
    }

    // ---------------- epilogue ----------------
    __half* bufQ = reinterpret_cast<__half*>(smc);           // [64][72]
    __half* bufK = reinterpret_cast<__half*>(smc + 9216);
    __half* bufV = reinterpret_cast<__half*>(smc + 18432);

#pragma unroll
    for (int mi = 0; mi < 3; mi++) {
        int row = wm + mi * 16;
        int p = row >> 6;
        int lr = (row & 63) + gid;
        const float* bias = p == 0 ? bq : (p == 1 ? bk : bv);
        __half* dst = p == 0 ? bufQ : (p == 1 ? bufK : bufV);
        float b0v = bias[lr], b1v = bias[lr + 8];
#pragma unroll
        for (int ni = 0; ni < 4; ni++) {
            int col = wn + ni * 8 + 2 * tig;
            sth2(dst + lr * 72 + col,       acc[mi][ni][0] + b0v, acc[mi][ni][1] + b0v);
            sth2(dst + (lr + 8) * 72 + col, acc[mi][ni][2] + b1v, acc[mi][ni][3] + b1v);
        }
    }
    __syncthreads();

    // V -> global
#pragma unroll
    for (int i = 0; i < 2; i++) {
        int v = tid + i * 256;
        int row = v >> 3, c = v & 7;
        uint4 t = *reinterpret_cast<const uint4*>(bufV + row * 72 + c * 8);
        *reinterpret_cast<uint4*>(g_V + ((size_t)b * CPD + row) * NN + n0 + c * 8) = t;
    }

    // energy: E(64,64) = K(64ch x 64n) @ Q(64ch x 64n)^T, 8 warps (4m x 2n)
    {
        const int wmE = (warp & 3) * 16;
        const int wnE = (warp >> 2) * 32;
        const uint32_t kBase = smcBase + 9216;
        const uint32_t qBase = smcBase;
        float accE[4][4];
#pragma unroll
        for (int j = 0; j < 4; j++)
#pragma unroll
            for (int q = 0; q < 4; q++) accE[j][q] = 0.f;

#pragma unroll
        for (int kk = 0; kk < 4; kk++) {
            uint32_t af[4], bt[2][4];
            ldsm_x4(af, kBase + (wmE + lrow) * 144 + kk * 32 + lkb);
#pragma unroll
            for (int t = 0; t < 2; t++)
                ldsm_x4(bt[t], qBase + (wnE + t * 16 + lrow) * 144 + kk * 32 + lkb);
#pragma unroll
            for (int ni = 0; ni < 4; ni++) {
                uint32_t bb[2] = { bt[ni >> 1][ni & 1], bt[ni >> 1][(ni & 1) + 2] };
                mma16(accE[ni], af, bb);
            }
        }

        float* P = g_P + (size_t)(b * 64 + blockIdx.x) * CPD * CPD;
        int r0 = wmE + gid;
#pragma unroll
        for (int ni = 0; ni < 4; ni++) {
            int cc = wnE + ni * 8 + 2 * tig;
            *reinterpret_cast<float2*>(P + (size_t)r0 * CPD + cc) =
                make_float2(accE[ni][0], accE[ni][1]);
            *reinterpret_cast<float2*>(P + (size_t)(r0 + 8) * CPD + cc) =
                make_float2(accE[ni][2], accE[ni][3]);
        }
    }
}

// ============================================================================
// K2a: reduce 64 partials + warp-per-row softmax -> g_E (normalized A).
// grid (8, 16), 256 threads = 8 warps; warp w owns row bx*8+w.
// ============================================================================
__global__ __launch_bounds__(256) void reduce_softmax_kernel()
{
    const int b = blockIdx.y;
    const int row = blockIdx.x * 8 + (threadIdx.x >> 5);
    const int lane = threadIdx.x & 31;
    const int i0 = row * 64 + lane;
    const int i1 = i0 + 32;

    float s0 = 0.f, s1 = 0.f;
#pragma unroll
    for (int p = 0; p < 64; p++) {
        const float* P = g_P + (size_t)(b * 64 + p) * 4096;
        s0 += P[i0];
        s1 += P[i1];
    }

    float m = fmaxf(s0, s1);
#pragma unroll
    for (int o = 16; o > 0; o >>= 1)
        m = fmaxf(m, __shfl_xor_sync(0xffffffffu, m, o));
    float e0 = __expf(s0 - m), e1 = __expf(s1 - m);
    float ssum = e0 + e1;
#pragma unroll
    for (int o = 16; o > 0; o >>= 1)
        ssum += __shfl_xor_sync(0xffffffffu, ssum, o);
    float inv = 1.f / ssum;

    g_E[(size_t)b * 4096 + i0] = e0 * inv;
    g_E[(size_t)b * 4096 + i1] = e1 * inv;
}

// ============================================================================
// K2b: pure momix M = Wo @ A. grid (16 chunks of 32 c-rows, 16 b) = 256 CTAs,
// 256 threads — halve per-CTA smem traffic, ~2 CTAs/SM.
// ============================================================================
__global__ __launch_bounds__(256) void momix_kernel(const float* __restrict__ wo)
{
    __shared__ float A[64][68];
    __shared__ float Wos[32][68];
    const int cg = blockIdx.x, b = blockIdx.y, tid = threadIdx.x;
    const int c0 = cg * 32;

    for (int idx = tid; idx < 4096; idx += 256)
        A[idx >> 6][idx & 63] = g_E[(size_t)b * 4096 + idx];
#pragma unroll
    for (int i = 0; i < 2; i++) {
        int v = tid + i * 256, m = v >> 4, kv = v & 15;
        *reinterpret_cast<float4*>(&Wos[m][kv * 4]) =
            *reinterpret_cast<const float4*>(wo + (size_t)(c0 + m) * CPD + kv * 4);
    }
    __syncthreads();

    const int cl = tid >> 3, jg = tid & 7;       // 32 rows x 8 j-groups
    float acc[8];
#pragma unroll
    for (int q = 0; q < 8; q++) acc[q] = 0.f;
#pragma unroll 8
    for (int o = 0; o < 64; o++) {
        float w = Wos[cl][o];
        const float4* ar = reinterpret_cast<const float4*>(&A[o][jg * 8]);
        float4 a0 = ar[0], a1 = ar[1];
        acc[0] += w * a0.x; acc[1] += w * a0.y; acc[2] += w * a0.z; acc[3] += w * a0.w;
        acc[4] += w * a1.x; acc[5] += w * a1.y; acc[6] += w * a1.z; acc[7] += w * a1.w;
    }
    __half2 h0 = __floats2half2_rn(acc[0], acc[1]);
    __half2 h1 = __floats2half2_rn(acc[2], acc[3]);
    __half2 h2 = __floats2half2_rn(acc[4], acc[5]);
    __half2 h3 = __floats2half2_rn(acc[6], acc[7]);
    uint4 u;
    u.x = *reinterpret_cast<uint32_t*>(&h0);
    u.y = *reinterpret_cast<uint32_t*>(&h1);
    u.z = *reinterpret_cast<uint32_t*>(&h2);
    u.w = *reinterpret_cast<uint32_t*>(&h3);
    *reinterpret_cast<uint4*>(g_M + ((size_t)b * CC + c0 + cl) * CPD + jg * 8) = u;
}

// ============================================================================
// K4: Y = gamma*(M @ V + bo) + X.  [fp16 mma + ldmatrix, float4 epilogue]
// grid (32 n-tiles, 16 b, 4 c-quarters), 256 threads (8 warps: 2m x 4n).
// ============================================================================
#define K4_SMEMB 70656

__global__ __launch_bounds__(256) void out_kernel(
    const float* __restrict__ x, const float* __restrict__ bo,
    const float* __restrict__ gamma, float* __restrict__ y)
{
    extern __shared__ char smc4[];
    __half* Vt = reinterpret_cast<__half*>(smc4);            // [128][72]
    __half* Ms = reinterpret_cast<__half*>(smc4 + 18432);    // [2][64][72]
    float*  Ys = reinterpret_cast<float*>(smc4 + 36864);     // [64][132]
    __half* Vraw = reinterpret_cast<__half*>(smc4 + 36864);  // [64][136] overlay

    const int n0 = blockIdx.x * 128, b = blockIdx.y;
    const int cb = blockIdx.z * 128;
    const int tid = threadIdx.x, lane = tid & 31, warp = tid >> 5;
    const int wm = (warp & 1) * 32, wn = (warp >> 1) * 32;
    const int gid = lane >> 2, tig = lane & 3;
    const int lrow = lane & 15, lkb = (lane >> 4) * 16;

#pragma unroll
    for (int i = 0; i < 4; i++) {
        int v = tid + i * 256, r = v >> 4, sg = v & 15;
        cp_async16(Vraw + r * 136 + sg * 8,
                   g_V + ((size_t)b * CPD + r) * NN + n0 + sg * 8);
    }
#pragma unroll
    for (int i = 0; i < 2; i++) {
        int v = tid + i * 256, r = v >> 3, sg = v & 7;
        cp_async16(Ms + r * 72 + sg * 8,
                   g_M + ((size_t)b * CC + cb + r) * CPD + sg * 8);
    }
    CP_COMMIT();
    CP_WAIT(0);
    __syncthreads();

    {
        const int n = tid & 127, cph = tid >> 7;
#pragma unroll
        for (int j = 0; j < 16; j++) {
            int cp = 2 * cph + 4 * j;
            __half a = Vraw[cp * 136 + n];
            __half c = Vraw[(cp + 1) * 136 + n];
            *reinterpret_cast<__half2*>(Vt + n * 72 + cp) = __halves2half2(a, c);
        }
    }
    __syncthreads();

    const float g = gamma[0];
    const uint32_t vtBase = (uint32_t)__cvta_generic_to_shared(Vt);
    const uint32_t msBase = (uint32_t)__cvta_generic_to_shared(Ms);

    for (int ch = 0; ch < 2; ch++) {
        const int buf = ch & 1;
        const int c0 = cb + ch * 64;
        if (ch < 1) {
            __half* Md = Ms + 4608;
#pragma unroll
            for (int i = 0; i < 2; i++) {
                int v = tid + i * 256, r = v >> 3, sg = v & 7;
                cp_async16(Md + r * 72 + sg * 8,
                           g_M + ((size_t)b * CC + c0 + 64 + r) * CPD + sg * 8);
            }
            CP_COMMIT();
            CP_WAIT(1);
        } else {
            CP_WAIT(0);
        }
        __syncthreads();

        float acc[2][4][4];
#pragma unroll
        for (int i = 0; i < 2; i++)
#pragma unroll
            for (int j = 0; j < 4; j++)
#pragma unroll
                for (int q = 0; q < 4; q++) acc[i][j][q] = 0.f;

        const uint32_t aBase = msBase + buf * 9216;
#pragma unroll
        for (int kk = 0; kk < 4; kk++) {
            uint32_t af[2][4], bt[2][4];
#pragma unroll
            for (int mi = 0; mi < 2; mi++)
                ldsm_x4(af[mi], aBase + (wm + mi * 16 + lrow) * 144 + kk * 32 + lkb);
#pragma unroll
            for (int t = 0; t < 2; t++)
                ldsm_x4(bt[t], vtBase + (wn + t * 16 + lrow) * 144 + kk * 32 + lkb);
#pragma unroll
            for (int mi = 0; mi < 2; mi++)
#pragma unroll
                for (int ni = 0; ni < 4; ni++) {
                    uint32_t bb[2] = { bt[ni >> 1][ni & 1], bt[ni >> 1][(ni & 1) + 2] };
                    mma16(acc[mi][ni], af[mi], bb);
                }
        }

#pragma unroll
        for (int mi = 0; mi < 2; mi++) {
            int r0 = wm + mi * 16 + gid;
            float bo0 = bo[c0 + r0], bo1 = bo[c0 + r0 + 8];
#pragma unroll
            for (int ni = 0; ni < 4; ni++) {
                int col = wn + ni * 8 + 2 * tig;
                *reinterpret_cast<float2*>(Ys + r0 * 132 + col) =
                    make_float2(g * (acc[mi][ni][0] + bo0), g * (acc[mi][ni][1] + bo0));
                *reinterpret_cast<float2*>(Ys + (r0 + 8) * 132 + col) =
                    make_float2(g * (acc[mi][ni][2] + bo1), g * (acc[mi][ni][3] + bo1));
            }
        }
        __syncthreads();

#pragma unroll
        for (int i = 0; i < 8; i++) {
            int v = tid + i * 256;
            int row = v >> 5, c4 = (v & 31) * 4;
            size_t off = ((size_t)b * CC + c0 + row) * NN + n0 + c4;
            float4 xv = *reinterpret_cast<const float4*>(x + off);
            float4 yv = *reinterpret_cast<const float4*>(Ys + row * 132 + c4);
            yv.x += xv.x; yv.y += xv.y; yv.z += xv.z; yv.w += xv.w;
            *reinterpret_cast<float4*>(y + off) = yv;
        }
        __syncthreads();
    }
}

// ============================================================================
extern "C" void kernel_launch(void* const* d_in, const int* in_sizes, int n_in,
                              void* d_out, int out_size)
{
    const float* x  = (const float*)d_in[0];
    const float* wq = (const float*)d_in[1];
    const float* bq = (const float*)d_in[2];
    const float* wk = (const float*)d_in[3];
    const float* bk = (const float*)d_in[4];
    const float* wv = (const float*)d_in[5];
    const float* bv = (const float*)d_in[6];
    const float* wo = (const float*)d_in[7];
    const float* bo = (const float*)d_in[8];
    const float* gm = (const float*)d_in[9];
    float* y = (float*)d_out;

    static int inited = 0;
    if (!inited) {
        cudaFuncSetAttribute(qkv_energy_kernel, cudaFuncAttributeMaxDynamicSharedMemorySize,
                             K1_SMEMB);
        cudaFuncSetAttribute(out_kernel, cudaFuncAttributeMaxDynamicSharedMemorySize,
                             K4_SMEMB);
        inited = 1;
    }

    wconv_kernel<<<96, 256>>>(wq, wk, wv);
    qkv_energy_kernel<<<dim3(64, 16), 256, K1_SMEMB>>>(x, bq, bk, bv);
    reduce_softmax_kernel<<<dim3(8, 16), 256>>>();
    momix_kernel<<<dim3(16, 16), 256>>>(wo);
    out_kernel<<<dim3(32, 16, 4), 256, K4_SMEMB>>>(x, bo, gm, y);
}

// round 17
// speedup vs baseline: 1.0308x; 1.0308x over previous
#include <cuda_runtime.h>
#include <cuda_fp16.h>
#include <cstdint>

#define NB 16
#define CC 512
#define CPD 64
#define NN 4096

// scratch (static __device__ — no allocation)
__device__ __half g_V[(size_t)NB * CPD * NN];
__device__ float  g_P[(size_t)NB * 64 * CPD * CPD]; // energy partials (64 n-slices)
__device__ __half g_Ah[NB * CPD * CPD];             // softmaxed A, TRANSPOSED [j][o], fp16
__device__ __half g_W[192 * 512];                   // fp16 Wqkv
__device__ __half g_Woh[CC * CPD];                  // fp16 Wo (512 x 64)

__device__ __forceinline__ void cp_async16(void* smem, const void* gmem) {
    uint32_t s = (uint32_t)__cvta_generic_to_shared(smem);
    asm volatile("cp.async.cg.shared.global [%0], [%1], 16;\n" :: "r"(s), "l"(gmem));
}
#define CP_COMMIT() asm volatile("cp.async.commit_group;\n" ::: "memory")
#define CP_WAIT(n)  asm volatile("cp.async.wait_group %0;\n" :: "n"(n) : "memory")

__device__ __forceinline__ void mma16(float c[4], const uint32_t a[4], const uint32_t b[2]) {
    asm volatile(
        "mma.sync.aligned.m16n8k16.row.col.f32.f16.f16.f32 "
        "{%0,%1,%2,%3},{%4,%5,%6,%7},{%8,%9},{%0,%1,%2,%3};"
        : "+f"(c[0]), "+f"(c[1]), "+f"(c[2]), "+f"(c[3])
        : "r"(a[0]), "r"(a[1]), "r"(a[2]), "r"(a[3]), "r"(b[0]), "r"(b[1]));
}

__device__ __forceinline__ void ldsm_x4(uint32_t r[4], uint32_t smaddr) {
    asm volatile("ldmatrix.sync.aligned.m8n8.x4.shared.b16 {%0,%1,%2,%3}, [%4];"
        : "=r"(r[0]), "=r"(r[1]), "=r"(r[2]), "=r"(r[3]) : "r"(smaddr));
}

__device__ __forceinline__ void sth2(__half* p, float a, float b) {
    *reinterpret_cast<__half2*>(p) = __floats2half2_rn(a, b);
}

// ============================================================================
// K0a: convert Wqkv -> fp16 g_W. grid 96, 256 threads
// ============================================================================
__global__ __launch_bounds__(256) void wconv_kernel(
    const float* __restrict__ wq, const float* __restrict__ wk, const float* __restrict__ wv)
{
    int f = (blockIdx.x * 256 + threadIdx.x) * 4;
    int r = f >> 9, c = f & 511;
    const float* w = r < 64 ? wq + (size_t)r * 512
                   : r < 128 ? wk + (size_t)(r - 64) * 512
                             : wv + (size_t)(r - 128) * 512;
    float4 t = *reinterpret_cast<const float4*>(w + c);
    __half2 h0 = __floats2half2_rn(t.x, t.y);
    __half2 h1 = __floats2half2_rn(t.z, t.w);
    uint2 u;
    u.x = *reinterpret_cast<uint32_t*>(&h0);
    u.y = *reinterpret_cast<uint32_t*>(&h1);
    *reinterpret_cast<uint2*>(g_W + (size_t)r * 512 + c) = u;
}

// K0b: convert Wo -> fp16 g_Woh. grid 32, 256 threads (512*64 = 32768 floats)
__global__ __launch_bounds__(256) void woconv_kernel(const float* __restrict__ wo)
{
    int f = (blockIdx.x * 256 + threadIdx.x) * 4;
    float4 t = *reinterpret_cast<const float4*>(wo + f);
    __half2 h0 = __floats2half2_rn(t.x, t.y);
    __half2 h1 = __floats2half2_rn(t.z, t.w);
    uint2 u;
    u.x = *reinterpret_cast<uint32_t*>(&h0);
    u.y = *reinterpret_cast<uint32_t*>(&h1);
    *reinterpret_cast<uint2*>(g_Woh + f) = u;
}

// ============================================================================
// K1: fused QKV + energy. 256 threads (8 warps: 4m x 2n), tile 192x64, BK=32,
// 16 iters, triple-buffered A/S, double-buffered B. 2 CTAs/SM. (AT MAC FLOOR)
// ============================================================================
#define K1_AS(i) ((i) * 15360)
#define K1_SS(i) (46080 + (i) * 8704)
#define K1_BS(i) (72192 + (i) * 5120)
#define K1_SMEMB 82432

__device__ __forceinline__ void k1_transpose(char* smc, int s_slot, int b_buf, int tid) {
    const float* S = reinterpret_cast<const float*>(smc + K1_SS(s_slot));
    __half* Bd = reinterpret_cast<__half*>(smc + K1_BS(b_buf));
    const int n = tid & 63, kb = (tid >> 6) * 8;
    const float* col = S + n;
    float v0 = col[(kb + 0) * 68], v1 = col[(kb + 1) * 68];
    float v2 = col[(kb + 2) * 68], v3 = col[(kb + 3) * 68];
    float v4 = col[(kb + 4) * 68], v5 = col[(kb + 5) * 68];
    float v6 = col[(kb + 6) * 68], v7 = col[(kb + 7) * 68];
    __half2 h0 = __floats2half2_rn(v0, v1), h1 = __floats2half2_rn(v2, v3);
    __half2 h2 = __floats2half2_rn(v4, v5), h3 = __floats2half2_rn(v6, v7);
    uint4 u;
    u.x = *reinterpret_cast<uint32_t*>(&h0);
    u.y = *reinterpret_cast<uint32_t*>(&h1);
    u.z = *reinterpret_cast<uint32_t*>(&h2);
    u.w = *reinterpret_cast<uint32_t*>(&h3);
    *reinterpret_cast<uint4*>(Bd + n * 40 + kb) = u;
}

__device__ __forceinline__ void k1_issue_stage(char* smc, int slot, int k0,
                                               const float* Xb, int n0, int tid) {
    char* Ad = smc + K1_AS(slot);
    char* Sd = smc + K1_SS(slot);
#pragma unroll
    for (int i = 0; i < 3; i++) {
        int v = tid + i * 256, r = v >> 2, kv = v & 3;
        cp_async16(Ad + r * 80 + kv * 16, g_W + (size_t)r * 512 + k0 + kv * 8);
    }
#pragma unroll
    for (int i = 0; i < 2; i++) {
        int v = tid + i * 256, k = v >> 4, nv = v & 15;
        cp_async16(Sd + k * 272 + nv * 16, Xb + (size_t)(k0 + k) * NN + n0 + nv * 4);
    }
    CP_COMMIT();
}

__global__ __launch_bounds__(256, 2) void qkv_energy_kernel(
    const float* __restrict__ x,
    const float* __restrict__ bq, const float* __restrict__ bk, const float* __restrict__ bv)
{
    extern __shared__ char smc[];
    const int b = blockIdx.y;
    const int n0 = blockIdx.x * 64;
    const float* Xb = x + (size_t)b * CC * NN;

    const int tid = threadIdx.x;
    const int lane = tid & 31, warp = tid >> 5;
    const int wm = (warp & 3) * 48;
    const int wn = (warp >> 2) * 32;
    const int gid = lane >> 2, tig = lane & 3;
    const int lrow = lane & 15, lkb = (lane >> 4) * 16;

    float acc[3][4][4];
#pragma unroll
    for (int i = 0; i < 3; i++)
#pragma unroll
        for (int j = 0; j < 4; j++)
#pragma unroll
            for (int q = 0; q < 4; q++) acc[i][j][q] = 0.f;

    k1_issue_stage(smc, 0, 0, Xb, n0, tid);
    k1_issue_stage(smc, 1, 32, Xb, n0, tid);
    k1_issue_stage(smc, 2, 64, Xb, n0, tid);
    CP_WAIT(2);
    __syncthreads();
    k1_transpose(smc, 0, 0, tid);
    __syncthreads();

    const uint32_t smcBase = (uint32_t)__cvta_generic_to_shared(smc);

    for (int kt = 0; kt < 16; kt++) {
        const int a_slot = kt % 3;
        const int bbuf = kt & 1;

        if (kt <= 13) { CP_WAIT(1); }
        else if (kt == 14) { CP_WAIT(0); }
        __syncthreads();

        if (kt < 15) k1_transpose(smc, (kt + 1) % 3, (kt + 1) & 1, tid);

        const uint32_t aBase = smcBase + K1_AS(a_slot);
        const uint32_t bBase = smcBase + K1_BS(bbuf);
#pragma unroll
        for (int kk = 0; kk < 2; kk++) {
            uint32_t af[3][4], bt[2][4];
#pragma unroll
            for (int mi = 0; mi < 3; mi++)
                ldsm_x4(af[mi], aBase + (wm + mi * 16 + lrow) * 80 + kk * 32 + lkb);
#pragma unroll
            for (int t = 0; t < 2; t++)
                ldsm_x4(bt[t], bBase + (wn + t * 16 + lrow) * 80 + kk * 32 + lkb);
#pragma unroll
            for (int mi = 0; mi < 3; mi++)
#pragma unroll
                for (int ni = 0; ni < 4; ni++) {
                    uint32_t bb[2] = { bt[ni >> 1][ni & 1], bt[ni >> 1][(ni & 1) + 2] };
                    mma16(acc[mi][ni], af[mi], bb);
                }
        }
        __syncthreads();

        if (kt <= 12)
            k1_issue_stage(smc, a_slot, (kt + 3) * 32, Xb, n0, tid);
    }

    // ---------------- epilogue ----------------
    __half* bufQ = reinterpret_cast<__half*>(smc);           // [64][72]
    __half* bufK = reinterpret_cast<__half*>(smc + 9216);
    __half* bufV = reinterpret_cast<__half*>(smc + 18432);

#pragma unroll
    for (int mi = 0; mi < 3; mi++) {
        int row = wm + mi * 16;
        int p = row >> 6;
        int lr = (row & 63) + gid;
        const float* bias = p == 0 ? bq : (p == 1 ? bk : bv);
        __half* dst = p == 0 ? bufQ : (p == 1 ? bufK : bufV);
        float b0v = bias[lr], b1v = bias[lr + 8];
#pragma unroll
        for (int ni = 0; ni < 4; ni++) {
            int col = wn + ni * 8 + 2 * tig;
            sth2(dst + lr * 72 + col,       acc[mi][ni][0] + b0v, acc[mi][ni][1] + b0v);
            sth2(dst + (lr + 8) * 72 + col, acc[mi][ni][2] + b1v, acc[mi][ni][3] + b1v);
        }
    }
    __syncthreads();

    // V -> global
#pragma unroll
    for (int i = 0; i < 2; i++) {
        int v = tid + i * 256;
        int row = v >> 3, c = v & 7;
        uint4 t = *reinterpret_cast<const uint4*>(bufV + row * 72 + c * 8);
        *reinterpret_cast<uint4*>(g_V + ((size_t)b * CPD + row) * NN + n0 + c * 8) = t;
    }

    // energy: E(64,64) = K(64ch x 64n) @ Q(64ch x 64n)^T, 8 warps (4m x 2n)
    {
        const int wmE = (warp & 3) * 16;
        const int wnE = (warp >> 2) * 32;
        const uint32_t kBase = smcBase + 9216;
        const uint32_t qBase = smcBase;
        float accE[4][4];
#pragma unroll
        for (int j = 0; j < 4; j++)
#pragma unroll
            for (int q = 0; q < 4; q++) accE[j][q] = 0.f;

#pragma unroll
        for (int kk = 0; kk < 4; kk++) {
            uint32_t af[4], bt[2][4];
            ldsm_x4(af, kBase + (wmE + lrow) * 144 + kk * 32 + lkb);
#pragma unroll
            for (int t = 0; t < 2; t++)
                ldsm_x4(bt[t], qBase + (wnE + t * 16 + lrow) * 144 + kk * 32 + lkb);
#pragma unroll
            for (int ni = 0; ni < 4; ni++) {
                uint32_t bb[2] = { bt[ni >> 1][ni & 1], bt[ni >> 1][(ni & 1) + 2] };
                mma16(accE[ni], af, bb);
            }
        }

        float* P = g_P + (size_t)(b * 64 + blockIdx.x) * CPD * CPD;
        int r0 = wmE + gid;
#pragma unroll
        for (int ni = 0; ni < 4; ni++) {
            int cc = wnE + ni * 8 + 2 * tig;
            *reinterpret_cast<float2*>(P + (size_t)r0 * CPD + cc) =
                make_float2(accE[ni][0], accE[ni][1]);
            *reinterpret_cast<float2*>(P + (size_t)(r0 + 8) * CPD + cc) =
                make_float2(accE[ni][2], accE[ni][3]);
        }
    }
}

// ============================================================================
// K2: reduce 64 partials + warp-per-row softmax -> g_Ah (A transposed, fp16).
// grid (8, 16), 256 threads = 8 warps; warp w owns row (o-index) bx*8+w.
// ============================================================================
__global__ __launch_bounds__(256) void reduce_softmax_kernel()
{
    const int b = blockIdx.y;
    const int row = blockIdx.x * 8 + (threadIdx.x >> 5);   // o index
    const int lane = threadIdx.x & 31;                      // j index
    const int i0 = row * 64 + lane;
    const int i1 = i0 + 32;

    float s0 = 0.f, s1 = 0.f;
#pragma unroll
    for (int p = 0; p < 64; p++) {
        const float* P = g_P + (size_t)(b * 64 + p) * 4096;
        s0 += P[i0];
        s1 += P[i1];
    }

    float m = fmaxf(s0, s1);
#pragma unroll
    for (int o = 16; o > 0; o >>= 1)
        m = fmaxf(m, __shfl_xor_sync(0xffffffffu, m, o));
    float e0 = __expf(s0 - m), e1 = __expf(s1 - m);
    float ssum = e0 + e1;
#pragma unroll
    for (int o = 16; o > 0; o >>= 1)
        ssum += __shfl_xor_sync(0xffffffffu, ssum, o);
    float inv = 1.f / ssum;

    // store TRANSPOSED: Ah[j][o] = A[o][j]
    g_Ah[(size_t)b * 4096 + lane * 64 + row]        = __float2half(e0 * inv);
    g_Ah[(size_t)b * 4096 + (lane + 32) * 64 + row] = __float2half(e1 * inv);
}

// ============================================================================
// K4: fused momix + output.
//   M(128,64) = Wo_chunk @ A   [fp16 mma, in prologue]
//   Y = gamma*(M @ V + bo) + X [fp16 mma + ldmatrix, float4 epilogue]
// grid (32 n-tiles, 16 b, 4 c-quarters), 256 threads (8 warps).
// smem bytes: Vt @0 (18432), Ms @18432 (18432), Wos @36864 (18432),
//             At @55296 (9216), Ys @64512 (33792); Vraw overlays Ys. tot 98304
// ============================================================================
#define K4_SMEMB 98304

__global__ __launch_bounds__(256) void out_kernel(
    const float* __restrict__ x, const float* __restrict__ bo,
    const float* __restrict__ gamma, float* __restrict__ y)
{
    extern __shared__ char smc4[];
    __half* Vt   = reinterpret_cast<__half*>(smc4);            // [128][72]
    __half* Ms   = reinterpret_cast<__half*>(smc4 + 18432);    // [128][72]
    __half* Wos  = reinterpret_cast<__half*>(smc4 + 36864);    // [128][72]
    __half* At   = reinterpret_cast<__half*>(smc4 + 55296);    // [64][72]
    float*  Ys   = reinterpret_cast<float*>(smc4 + 64512);     // [64][132]
    __half* Vraw = reinterpret_cast<__half*>(smc4 + 64512);    // [64][136] overlay

    const int n0 = blockIdx.x * 128, b = blockIdx.y;
    const int cb = blockIdx.z * 128;
    const int tid = threadIdx.x, lane = tid & 31, warp = tid >> 5;
    const int wm = (warp & 1) * 32, wn = (warp >> 1) * 32;
    const int gid = lane >> 2, tig = lane & 3;
    const int lrow = lane & 15, lkb = (lane >> 4) * 16;

    // prologue loads: Vraw + Wo chunk + At, one group
#pragma unroll
    for (int i = 0; i < 4; i++) {
        int v = tid + i * 256, r = v >> 4, sg = v & 15;
        cp_async16(Vraw + r * 136 + sg * 8,
                   g_V + ((size_t)b * CPD + r) * NN + n0 + sg * 8);
    }
#pragma unroll
    for (int i = 0; i < 4; i++) {
        int v = tid + i * 256, r = v >> 3, sg = v & 7;
        cp_async16(Wos + r * 72 + sg * 8, g_Woh + (size_t)(cb + r) * CPD + sg * 8);
    }
#pragma unroll
    for (int i = 0; i < 2; i++) {
        int v = tid + i * 256, r = v >> 3, sg = v & 7;
        cp_async16(At + r * 72 + sg * 8, g_Ah + (size_t)b * 4096 + r * 64 + sg * 8);
    }
    CP_COMMIT();
    CP_WAIT(0);
    __syncthreads();

    // transpose Vraw[cp][n] -> Vt[n][cp]
    {
        const int n = tid & 127, cph = tid >> 7;
#pragma unroll
        for (int j = 0; j < 16; j++) {
            int cp = 2 * cph + 4 * j;
            __half a = Vraw[cp * 136 + n];
            __half c = Vraw[(cp + 1) * 136 + n];
            *reinterpret_cast<__half2*>(Vt + n * 72 + cp) = __halves2half2(a, c);
        }
    }

    const uint32_t vtBase  = (uint32_t)__cvta_generic_to_shared(Vt);
    const uint32_t msBase  = (uint32_t)__cvta_generic_to_shared(Ms);
    const uint32_t wosBase = (uint32_t)__cvta_generic_to_shared(Wos);
    const uint32_t atBase  = (uint32_t)__cvta_generic_to_shared(At);

    // M = Wo_chunk(128x64) @ A(64x64): warp w does rows [w*16, w*16+16), all 64 j
    {
        const int wm2 = warp * 16;
        float accM[8][4];
#pragma unroll
        for (int j = 0; j < 8; j++)
#pragma unroll
            for (int q = 0; q < 4; q++) accM[j][q] = 0.f;

#pragma unroll
        for (int kk = 0; kk < 4; kk++) {
            uint32_t af[4], bt[4][4];
            ldsm_x4(af, wosBase + (wm2 + lrow) * 144 + kk * 32 + lkb);
#pragma unroll
            for (int t = 0; t < 4; t++)
                ldsm_x4(bt[t], atBase + (t * 16 + lrow) * 144 + kk * 32 + lkb);
#pragma unroll
            for (int ni = 0; ni < 8; ni++) {
                uint32_t bb[2] = { bt[ni >> 1][ni & 1], bt[ni >> 1][(ni & 1) + 2] };
                mma16(accM[ni], af, bb);
            }
        }
        int r0 = wm2 + gid;
#pragma unroll
        for (int ni = 0; ni < 8; ni++) {
            int col = ni * 8 + 2 * tig;
            sth2(Ms + r0 * 72 + col,       accM[ni][0], accM[ni][1]);
            sth2(Ms + (r0 + 8) * 72 + col, accM[ni][2], accM[ni][3]);
        }
    }
    __syncthreads();

    const float g = gamma[0];

    for (int ch = 0; ch < 2; ch++) {
        const int c0 = cb + ch * 64;
        const uint32_t aBase = msBase + ch * 9216;

        float acc[2][4][4];
#pragma unroll
        for (int i = 0; i < 2; i++)
#pragma unroll
            for (int j = 0; j < 4; j++)
#pragma unroll
                for (int q = 0; q < 4; q++) acc[i][j][q] = 0.f;

#pragma unroll
        for (int kk = 0; kk < 4; kk++) {
            uint32_t af[2][4], bt[2][4];
#pragma unroll
            for (int mi = 0; mi < 2; mi++)
                ldsm_x4(af[mi], aBase + (wm + mi * 16 + lrow) * 144 + kk * 32 + lkb);
#pragma unroll
            for (int t = 0; t < 2; t++)
                ldsm_x4(bt[t], vtBase + (wn + t * 16 + lrow) * 144 + kk * 32 + lkb);
#pragma unroll
            for (int mi = 0; mi < 2; mi++)
#pragma unroll
                for (int ni = 0; ni < 4; ni++) {
                    uint32_t bb[2] = { bt[ni >> 1][ni & 1], bt[ni >> 1][(ni & 1) + 2] };
                    mma16(acc[mi][ni], af[mi], bb);
                }
        }

        if (ch == 0) __syncthreads();   // Ys overlay: Vraw fully consumed by Vt already;
                                        // barrier separates chunk writes below from prior reads
#pragma unroll
        for (int mi = 0; mi < 2; mi++) {
            int r0 = wm + mi * 16 + gid;
            float bo0 = bo[c0 + r0], bo1 = bo[c0 + r0 + 8];
#pragma unroll
            for (int ni = 0; ni < 4; ni++) {
                int col = wn + ni * 8 + 2 * tig;
                *reinterpret_cast<float2*>(Ys + r0 * 132 + col) =
                    make_float2(g * (acc[mi][ni][0] + bo0), g * (acc[mi][ni][1] + bo0));
                *reinterpret_cast<float2*>(Ys + (r0 + 8) * 132 + col) =
                    make_float2(g * (acc[mi][ni][2] + bo1), g * (acc[mi][ni][3] + bo1));
            }
        }
        __syncthreads();

#pragma unroll
        for (int i = 0; i < 8; i++) {
            int v = tid + i * 256;
            int row = v >> 5, c4 = (v & 31) * 4;
            size_t off = ((size_t)b * CC + c0 + row) * NN + n0 + c4;
            float4 xv = *reinterpret_cast<const float4*>(x + off);
            float4 yv = *reinterpret_cast<const float4*>(Ys + row * 132 + c4);
            yv.x += xv.x; yv.y += xv.y; yv.z += xv.z; yv.w += xv.w;
            *reinterpret_cast<float4*>(y + off) = yv;
        }
        __syncthreads();
    }
}

// ============================================================================
extern "C" void kernel_launch(void* const* d_in, const int* in_sizes, int n_in,
                              void* d_out, int out_size)
{
    const float* x  = (const float*)d_in[0];
    const float* wq = (const float*)d_in[1];
    const float* bq = (const float*)d_in[2];
    const float* wk = (const float*)d_in[3];
    const float* bk = (const float*)d_in[4];
    const float* wv = (const float*)d_in[5];
    const float* bv = (const float*)d_in[6];
    const float* wo = (const float*)d_in[7];
    const float* bo = (const float*)d_in[8];
    const float* gm = (const float*)d_in[9];
    float* y = (float*)d_out;

    static int inited = 0;
    if (!inited) {
        cudaFuncSetAttribute(qkv_energy_kernel, cudaFuncAttributeMaxDynamicSharedMemorySize,
                             K1_SMEMB);
        cudaFuncSetAttribute(out_kernel, cudaFuncAttributeMaxDynamicSharedMemorySize,
                             K4_SMEMB);
        inited = 1;
    }

    wconv_kernel<<<96, 256>>>(wq, wk, wv);
    woconv_kernel<<<32, 256>>>(wo);
    qkv_energy_kernel<<<dim3(64, 16), 256, K1_SMEMB>>>(x, bq, bk, bv);
    reduce_softmax_kernel<<<dim3(8, 16), 256>>>();
    out_kernel<<<dim3(32, 16, 4), 256, K4_SMEMB>>>(x, bo, gm, y);
}